// round 14
// baseline (speedup 1.0000x reference)
#include <cuda_runtime.h>
#include <math.h>

#define BATCH 8
#define NPTS  256
#define CH    32
#define MODES 16
#define NLAY  4
#define HID   128

typedef unsigned long long u64;
typedef ulonglong2 u64x2;

__device__ __forceinline__ u64 pk(float lo, float hi) {
    u64 r; asm("mov.b64 %0, {%1, %2};" : "=l"(r) : "f"(lo), "f"(hi)); return r;
}
__device__ __forceinline__ void upk(u64 v, float& lo, float& hi) {
    asm("mov.b64 {%0, %1}, %2;" : "=f"(lo), "=f"(hi) : "l"(v));
}
__device__ __forceinline__ u64 fma2(u64 a, u64 b, u64 c) {
    u64 d; asm("fma.rn.f32x2 %0, %1, %2, %3;" : "=l"(d) : "l"(a), "l"(b), "l"(c)); return d;
}
__device__ __forceinline__ u64 mul2(u64 a, u64 b) { return fma2(a, b, 0ULL); }

__device__ float  g_h[BATCH*CH*NPTS*NPTS];
__device__ float2 g_A[BATCH*MODES*CH*NPTS];
__device__ float2 g_T2[BATCH*NPTS*MODES*CH];
__device__ float2 g_Wp[NLAY*MODES*MODES*CH*CH];
__device__ float  g_ctab[MODES*NPTS];
__device__ float  g_stab[MODES*NPTS];
__device__ float  g_ctT[NPTS*MODES];
__device__ float  g_stT[NPTS*MODES];

// r9 gelu2 (measured best): polynomial in f32x2, rcp/exp scalar intrinsics
__device__ __forceinline__ u64 gelu2(u64 v) {
    float v0, v1; upk(v, v0, v1);
    float x0 = fabsf(v0) * 0.7071067811865475f;
    float x1 = fabsf(v1) * 0.7071067811865475f;
    float t0 = __fdividef(1.0f, fmaf(0.3275911f, x0, 1.0f));
    float t1 = __fdividef(1.0f, fmaf(0.3275911f, x1, 1.0f));
    float e0 = -__expf(x0 * -x0);
    float e1 = -__expf(x1 * -x1);
    u64 t = pk(t0, t1);
    u64 p = fma2(t, pk(1.061405429f, 1.061405429f), pk(-1.453152027f, -1.453152027f));
    p = fma2(p, t, pk(1.421413741f, 1.421413741f));
    p = fma2(p, t, pk(-0.284496736f, -0.284496736f));
    p = fma2(p, t, pk(0.254829592f, 0.254829592f));
    p = mul2(p, t);
    u64 er = fma2(p, pk(e0, e1), pk(1.0f, 1.0f));
    er |= (v & 0x8000000080000000ULL);
    u64 u = fma2(er, pk(0.5f, 0.5f), pk(0.5f, 0.5f));
    return mul2(v, u);
}

__global__ void k_tables() {
    int k = blockIdx.x, y = threadIdx.x;
    int p = (k * y) & 255;
    float ang = (float)p * 0.024543692606170259f;
    float s, c; sincosf(ang, &s, &c);
    g_ctab[k*NPTS+y] = c;   g_stab[k*NPTS+y] = s;
    g_ctT[y*MODES+k] = c;   g_stT[y*MODES+k] = s;
}

__global__ void k_repack(const float* __restrict__ wr, const float* __restrict__ wi) {
    int blk = blockIdx.x;
    int l = blk >> 5, i = blk & 31;
    const float* wrb = wr + (size_t)blk * CH * MODES * MODES;
    const float* wib = wi + (size_t)blk * CH * MODES * MODES;
    for (int idx = threadIdx.x; idx < MODES*MODES*CH; idx += blockDim.x) {
        int o = idx & 31, kx = (idx >> 5) & 15, ky = idx >> 9;
        int s = o*(MODES*MODES) + kx*MODES + ky;
        g_Wp[(((size_t)(l*MODES+ky)*MODES+kx)*CH + i)*CH + o] = make_float2(wrb[s], wib[s]);
    }
}

__global__ void k_lift(const float* __restrict__ bc, const float* __restrict__ xin,
                       const float* __restrict__ yin, const float* __restrict__ mw,
                       const float* __restrict__ mb) {
    int blk = blockIdx.x;
    int b = blk >> 8, xi = blk & 255;
    int y = threadIdx.x;
    float b0 = bc[b*3+0], b1 = bc[b*3+1], b2 = bc[b*3+2];
    float xv = xin[(b*NPTS+xi)*NPTS + y];
    float yv = yin[(b*NPTS+xi)*NPTS + y];
    #pragma unroll
    for (int c = 0; c < CH; c++) {
        float h = mb[c] + b0*mw[c] + b1*mw[32+c] + b2*mw[64+c] + xv*mw[96+c] + yv*mw[128+c];
        g_h[((size_t)(b*CH+c)*NPTS + xi)*NPTS + y] = h;
    }
}

// fwd y-DFT: 2 modes (ks, ks+8) x 4 rows per thread; rotation recurrence, no smem
__global__ __launch_bounds__(128) void k_fwd() {
    int tid = threadIdx.x;
    int blk = blockIdx.x;
    int xt = blk & 3;
    int bcIdx = blk >> 2;
    int ks = tid & 7;
    int xg = tid >> 3;
    int x0 = xt*64 + xg*4;
    const float4* h4 = (const float4*)(g_h + ((size_t)bcIdx*NPTS + x0)*NPTS);

    u64 cA[2], sA[2], cB[2], sB[2], C4[2], S4[2], nS4[2];
    #pragma unroll
    for (int m = 0; m < 2; m++) {
        float th = (float)(ks + 8*m) * 0.024543692606170259f;
        float c1,s1,c2,s2,c3,s3,c4,s4;
        sincosf(th,&s1,&c1);       sincosf(2.f*th,&s2,&c2);
        sincosf(3.f*th,&s3,&c3);   sincosf(4.f*th,&s4,&c4);
        cA[m]=pk(1.f,c1); sA[m]=pk(0.f,s1); cB[m]=pk(c2,c3); sB[m]=pk(s2,s3);
        C4[m]=pk(c4,c4);  S4[m]=pk(s4,s4);  nS4[m]=pk(-s4,-s4);
    }
    u64 ar[4][2] = {{0,0},{0,0},{0,0},{0,0}};
    u64 ai[4][2] = {{0,0},{0,0},{0,0},{0,0}};
    #pragma unroll 2
    for (int j = 0; j < 64; j++) {
        #pragma unroll
        for (int r = 0; r < 4; r++) {
            float4 v = h4[r*64 + j];
            u64 hlo = pk(v.x,v.y), hhi = pk(v.z,v.w);
            #pragma unroll
            for (int m = 0; m < 2; m++) {
                ar[r][m] = fma2(hlo, cA[m], ar[r][m]);
                ai[r][m] = fma2(hlo, sA[m], ai[r][m]);
                ar[r][m] = fma2(hhi, cB[m], ar[r][m]);
                ai[r][m] = fma2(hhi, sB[m], ai[r][m]);
            }
        }
        #pragma unroll
        for (int m = 0; m < 2; m++) {
            u64 cAn = mul2(cA[m], C4[m]); cAn = fma2(sA[m], nS4[m], cAn);
            u64 sAn = mul2(sA[m], C4[m]); sAn = fma2(cA[m], S4[m],  sAn);
            u64 cBn = mul2(cB[m], C4[m]); cBn = fma2(sB[m], nS4[m], cBn);
            u64 sBn = mul2(sB[m], C4[m]); sBn = fma2(cB[m], S4[m],  sBn);
            cA[m]=cAn; sA[m]=sAn; cB[m]=cBn; sB[m]=sBn;
        }
    }
    int b = bcIdx >> 5, c = bcIdx & 31;
    #pragma unroll
    for (int m = 0; m < 2; m++) {
        int ky = ks + 8*m;
        float2* outp = g_A + ((size_t)(b*MODES+ky)*CH + c)*NPTS + x0;
        #pragma unroll
        for (int r = 0; r < 4; r++) {
            float rl, rh, il, ih;
            upk(ar[r][m], rl, rh); upk(ai[r][m], il, ih);
            outp[r] = make_float2(rl + rh, -(il + ih));
        }
    }
}

__global__ __launch_bounds__(512) void k_spec(int layer) {
    __shared__ float2 Hft[CH*MODES];
    __shared__ float  Tmr[CH*17];
    __shared__ float  Tmi[CH*17];
    int tid = threadIdx.x;
    int b = blockIdx.x >> 4, ky = blockIdx.x & 15;
    {
        int c = tid >> 4, kx = tid & 15;
        const float2* Arow = g_A + ((size_t)(b*MODES+ky)*CH + c)*NPTS;
        float ar = 0.f, ai = 0.f;
        #pragma unroll 4
        for (int x = 0; x < 256; x++) {
            float2 a = Arow[x];
            float cc = g_ctT[x*16+kx], sv = g_stT[x*16+kx];
            ar += a.x*cc + a.y*sv;
            ai += a.y*cc - a.x*sv;
        }
        Hft[c*16+kx] = make_float2(ar*(1.0f/256.0f), ai*(1.0f/256.0f));
    }
    __syncthreads();
    {
        int kx = tid >> 5, o = tid & 31;
        const float2* W = g_Wp + ((size_t)((layer*MODES+ky)*MODES + kx)*CH)*CH;
        float tr = 0.f, ti = 0.f;
        #pragma unroll 8
        for (int i = 0; i < CH; i++) {
            float2 hh = Hft[i*16+kx];
            float2 w = W[i*32+o];
            tr += hh.x*w.x - hh.y*w.y;
            ti += hh.x*w.y + hh.y*w.x;
        }
        Tmr[o*17+kx] = tr;
        Tmi[o*17+kx] = ti;
    }
    __syncthreads();
    {
        int xg = tid >> 5, o = tid & 31;
        float Tr[16], Ti[16];
        #pragma unroll
        for (int k = 0; k < 16; k++) { Tr[k] = Tmr[o*17+k]; Ti[k] = Tmi[o*17+k]; }
        float scale = (ky == 0) ? (1.0f/256.0f) : (2.0f/256.0f);
        for (int j = 0; j < 16; j++) {
            int x = xg*16 + j;
            float br = 0.f, bi = 0.f;
            #pragma unroll
            for (int k = 0; k < 16; k++) {
                float cc = g_ctT[x*16+k], sv = g_stT[x*16+k];
                br += Tr[k]*cc - Ti[k]*sv;
                bi += Tr[k]*sv + Ti[k]*cc;
            }
            g_T2[((size_t)(b*NPTS+x)*MODES + ky)*CH + o] = make_float2(br*scale, bi*scale);
        }
    }
}

// combine: 64 threads, 4 y-points/thread, o-pair packed acc[4][16];
// h streamed from global (not preloaded) -> regs ~180, balanced wf:fma
__global__ __launch_bounds__(64) void k_layer(const float* __restrict__ pww,
                                              const float* __restrict__ pwb, int layer) {
    __shared__ __align__(16) float T2r[MODES*CH];
    __shared__ __align__(16) float T2i[MODES*CH];
    __shared__ __align__(16) float wsP[CH*CH];
    __shared__ __align__(8)  float pbs[CH];
    int tid = threadIdx.x;
    int b = blockIdx.x >> 8, x = blockIdx.x & 255;

    {
        const float2* src = g_T2 + (size_t)(b*NPTS + x)*MODES*CH;
        #pragma unroll
        for (int t = 0; t < 8; t++) {
            float2 v = src[tid + 64*t];
            T2r[tid + 64*t] = v.x; T2i[tid + 64*t] = v.y;
        }
    }
    for (int idx = tid; idx < CH*CH; idx += 64) {
        int o = idx >> 5, i = idx & 31;
        wsP[i*32 + o] = pww[layer*CH*CH + idx];
    }
    if (tid < CH) pbs[tid] = pwb[layer*CH + tid];
    __syncthreads();

    int y0 = 4*tid;
    u64 acc[4][16];
    #pragma unroll
    for (int op = 0; op < 16; op++) {
        u64 bb = *(const u64*)&pbs[2*op];
        acc[0][op] = bb; acc[1][op] = bb; acc[2][op] = bb; acc[3][op] = bb;
    }

    // pointwise: h streamed per i (LDG.128 of 4 consecutive y)
    #pragma unroll 1
    for (int i = 0; i < CH; i++) {
        float4 hv = *(const float4*)(g_h + ((size_t)(b*CH+i)*NPTS + x)*NPTS + y0);
        u64 hd0 = pk(hv.x,hv.x), hd1 = pk(hv.y,hv.y), hd2 = pk(hv.z,hv.z), hd3 = pk(hv.w,hv.w);
        #pragma unroll
        for (int q = 0; q < 8; q++) {
            u64x2 w = *(const u64x2*)&wsP[i*32 + 4*q];
            acc[0][2*q]   = fma2(hd0, w.x, acc[0][2*q]);
            acc[0][2*q+1] = fma2(hd0, w.y, acc[0][2*q+1]);
            acc[1][2*q]   = fma2(hd1, w.x, acc[1][2*q]);
            acc[1][2*q+1] = fma2(hd1, w.y, acc[1][2*q+1]);
            acc[2][2*q]   = fma2(hd2, w.x, acc[2][2*q]);
            acc[2][2*q+1] = fma2(hd2, w.y, acc[2][2*q+1]);
            acc[3][2*q]   = fma2(hd3, w.x, acc[3][2*q]);
            acc[3][2*q+1] = fma2(hd3, w.y, acc[3][2*q+1]);
        }
    }
    // inverse y-DFT: acc += cos*T2r + (-sin)*T2i
    #pragma unroll 1
    for (int k = 0; k < 16; k++) {
        float4 cv = *(const float4*)&g_ctab[k*NPTS + y0];
        float4 sv = *(const float4*)&g_stab[k*NPTS + y0];
        u64 cd0 = pk(cv.x,cv.x), cd1 = pk(cv.y,cv.y), cd2 = pk(cv.z,cv.z), cd3 = pk(cv.w,cv.w);
        u64 sd0 = pk(-sv.x,-sv.x), sd1 = pk(-sv.y,-sv.y), sd2 = pk(-sv.z,-sv.z), sd3 = pk(-sv.w,-sv.w);
        #pragma unroll
        for (int q = 0; q < 8; q++) {
            u64x2 tr = *(const u64x2*)&T2r[k*32 + 4*q];
            u64x2 ti = *(const u64x2*)&T2i[k*32 + 4*q];
            acc[0][2*q]   = fma2(cd0, tr.x, acc[0][2*q]);   acc[0][2*q]   = fma2(sd0, ti.x, acc[0][2*q]);
            acc[0][2*q+1] = fma2(cd0, tr.y, acc[0][2*q+1]); acc[0][2*q+1] = fma2(sd0, ti.y, acc[0][2*q+1]);
            acc[1][2*q]   = fma2(cd1, tr.x, acc[1][2*q]);   acc[1][2*q]   = fma2(sd1, ti.x, acc[1][2*q]);
            acc[1][2*q+1] = fma2(cd1, tr.y, acc[1][2*q+1]); acc[1][2*q+1] = fma2(sd1, ti.y, acc[1][2*q+1]);
            acc[2][2*q]   = fma2(cd2, tr.x, acc[2][2*q]);   acc[2][2*q]   = fma2(sd2, ti.x, acc[2][2*q]);
            acc[2][2*q+1] = fma2(cd2, tr.y, acc[2][2*q+1]); acc[2][2*q+1] = fma2(sd2, ti.y, acc[2][2*q+1]);
            acc[3][2*q]   = fma2(cd3, tr.x, acc[3][2*q]);   acc[3][2*q]   = fma2(sd3, ti.x, acc[3][2*q]);
            acc[3][2*q+1] = fma2(cd3, tr.y, acc[3][2*q+1]); acc[3][2*q+1] = fma2(sd3, ti.y, acc[3][2*q+1]);
        }
    }
    // epilogue: gelu + residual (h re-read) + store; per o-pair: 2 channel rows of 4 y
    #pragma unroll 1
    for (int op = 0; op < 16; op++) {
        u64 g0 = gelu2(acc[0][op]), g1 = gelu2(acc[1][op]);
        u64 g2 = gelu2(acc[2][op]), g3 = gelu2(acc[3][op]);
        float a0,b0v,a1,b1v,a2,b2v,a3,b3v;
        upk(g0,a0,b0v); upk(g1,a1,b1v); upk(g2,a2,b2v); upk(g3,a3,b3v);
        float* r0 = g_h + ((size_t)(b*CH + 2*op)*NPTS + x)*NPTS + y0;
        float* r1 = r0 + (size_t)NPTS*NPTS;
        float4 h0 = *(float4*)r0;
        float4 h1 = *(float4*)r1;
        *(float4*)r0 = make_float4(h0.x+a0, h0.y+a1, h0.z+a2, h0.w+a3);
        *(float4*)r1 = make_float4(h1.x+b0v, h1.y+b1v, h1.z+b2v, h1.w+b3v);
    }
}

// decoders: one d per blockIdx.y; 64 threads, 4 points/thread (measured-good r9 version)
__global__ __launch_bounds__(64) void k_dec(
        const float* __restrict__ w1, const float* __restrict__ b1,
        const float* __restrict__ w2, const float* __restrict__ b2,
        const float* __restrict__ w3, const float* __restrict__ b3,
        float* __restrict__ out) {
    __shared__ __align__(16) u64 W1d[CH*CH];
    __shared__ __align__(16) u64 W2d[CH*HID];
    __shared__ __align__(16) u64 W3d[HID];
    __shared__ __align__(16) u64 B1d[CH];
    __shared__ __align__(16) u64 B2d[HID];
    int tid = threadIdx.x;
    int b = blockIdx.x >> 8, x = blockIdx.x & 255;
    int d = blockIdx.y;
    int y0 = 4*tid;

    for (int idx = tid; idx < CH*CH; idx += 64) {
        float w = w1[d*CH*CH + idx]; W1d[idx] = pk(w, w);
    }
    for (int idx = tid; idx < CH*HID; idx += 64) {
        float w = w2[d*CH*HID + idx]; W2d[idx] = pk(w, w);
    }
    for (int idx = tid; idx < HID; idx += 64) {
        float w = w3[d*HID + idx]; W3d[idx] = pk(w, w);
        float bb = b2[d*HID + idx]; B2d[idx] = pk(bb, bb);
    }
    if (tid < CH) { float bb = b1[d*CH + tid]; B1d[tid] = pk(bb, bb); }
    __syncthreads();

    u64 z0[CH], z1p[CH];
    #pragma unroll
    for (int pp = 0; pp < 2; pp++) {
        u64 hd[CH];
        #pragma unroll
        for (int i = 0; i < CH; i++)
            hd[i] = *(const u64*)(g_h + ((size_t)(b*CH+i)*NPTS + x)*NPTS + y0 + 2*pp);
        u64* z = pp ? z1p : z0;
        #pragma unroll 2
        for (int jp = 0; jp < CH/2; jp++) {
            u64 a0 = B1d[2*jp], a1 = B1d[2*jp+1];
            #pragma unroll
            for (int i = 0; i < CH; i++) {
                u64x2 w = *(const u64x2*)&W1d[i*CH + 2*jp];
                a0 = fma2(hd[i], w.x, a0);
                a1 = fma2(hd[i], w.y, a1);
            }
            z[2*jp]   = gelu2(a0);
            z[2*jp+1] = gelu2(a1);
        }
    }
    u64 o20 = 0, o21 = 0;
    #pragma unroll 2
    for (int jp = 0; jp < HID/2; jp++) {
        u64 a00 = B2d[2*jp], a01 = B2d[2*jp+1];
        u64 a10 = a00, a11 = a01;
        #pragma unroll
        for (int i = 0; i < CH; i++) {
            u64x2 w = *(const u64x2*)&W2d[i*HID + 2*jp];
            a00 = fma2(z0[i],  w.x, a00);
            a01 = fma2(z0[i],  w.y, a01);
            a10 = fma2(z1p[i], w.x, a10);
            a11 = fma2(z1p[i], w.y, a11);
        }
        o20 = fma2(gelu2(a00), W3d[2*jp],   o20);
        o20 = fma2(gelu2(a01), W3d[2*jp+1], o20);
        o21 = fma2(gelu2(a10), W3d[2*jp],   o21);
        o21 = fma2(gelu2(a11), W3d[2*jp+1], o21);
    }
    float r0, r1, r2, r3;
    upk(o20, r0, r1); upk(o21, r2, r3);
    float bias3 = b3[d];
    size_t p = ((size_t)(b*NPTS + x))*NPTS + y0;
    out[p*3 + d]       = r0 + bias3;
    out[(p+1)*3 + d]   = r1 + bias3;
    out[(p+2)*3 + d]   = r2 + bias3;
    out[(p+3)*3 + d]   = r3 + bias3;
}

extern "C" void kernel_launch(void* const* d_in, const int* in_sizes, int n_in,
                              void* d_out, int out_size) {
    const float* bc      = (const float*)d_in[0];
    const float* xin     = (const float*)d_in[1];
    const float* yin     = (const float*)d_in[2];
    const float* mlp1_w  = (const float*)d_in[3];
    const float* mlp1_b  = (const float*)d_in[4];
    const float* spec_wr = (const float*)d_in[5];
    const float* spec_wi = (const float*)d_in[6];
    const float* pw_w    = (const float*)d_in[7];
    const float* pw_b    = (const float*)d_in[8];
    const float* dec_w1  = (const float*)d_in[9];
    const float* dec_b1  = (const float*)d_in[10];
    const float* dec_w2  = (const float*)d_in[11];
    const float* dec_b2  = (const float*)d_in[12];
    const float* dec_w3  = (const float*)d_in[13];
    const float* dec_b3  = (const float*)d_in[14];
    float* out = (float*)d_out;

    k_tables<<<16, 256>>>();
    k_repack<<<NLAY*CH, 256>>>(spec_wr, spec_wi);
    k_lift<<<BATCH*NPTS, 256>>>(bc, xin, yin, mlp1_w, mlp1_b);
    for (int l = 0; l < NLAY; l++) {
        k_fwd<<<BATCH*CH*4, 128>>>();
        k_spec<<<BATCH*MODES, 512>>>(l);
        k_layer<<<BATCH*NPTS, 64>>>(pw_w, pw_b, l);
    }
    dim3 dgrid(BATCH*NPTS, 3);
    k_dec<<<dgrid, 64>>>(dec_w1, dec_b1, dec_w2, dec_b2, dec_w3, dec_b3, out);
}

// round 15
// speedup vs baseline: 1.2631x; 1.2631x over previous
#include <cuda_runtime.h>
#include <math.h>

#define BATCH 8
#define NPTS  256
#define CH    32
#define MODES 16
#define NLAY  4
#define HID   128

typedef unsigned long long u64;
typedef ulonglong2 u64x2;

__device__ __forceinline__ u64 pk(float lo, float hi) {
    u64 r; asm("mov.b64 %0, {%1, %2};" : "=l"(r) : "f"(lo), "f"(hi)); return r;
}
__device__ __forceinline__ void upk(u64 v, float& lo, float& hi) {
    asm("mov.b64 {%0, %1}, %2;" : "=f"(lo), "=f"(hi) : "l"(v));
}
__device__ __forceinline__ u64 fma2(u64 a, u64 b, u64 c) {
    u64 d; asm("fma.rn.f32x2 %0, %1, %2, %3;" : "=l"(d) : "l"(a), "l"(b), "l"(c)); return d;
}
__device__ __forceinline__ u64 mul2(u64 a, u64 b) { return fma2(a, b, 0ULL); }

__device__ float  g_h[BATCH*CH*NPTS*NPTS];
__device__ float2 g_A[BATCH*MODES*CH*NPTS];
__device__ float2 g_T2[BATCH*NPTS*MODES*CH];
__device__ float2 g_Wp[NLAY*MODES*MODES*CH*CH];
__device__ float  g_ctab[MODES*NPTS];
__device__ float  g_stab[MODES*NPTS];
__device__ float  g_ctT[NPTS*MODES];
__device__ float  g_stT[NPTS*MODES];

// r9 gelu2 (measured best): polynomial in f32x2, rcp/exp scalar intrinsics
__device__ __forceinline__ u64 gelu2(u64 v) {
    float v0, v1; upk(v, v0, v1);
    float x0 = fabsf(v0) * 0.7071067811865475f;
    float x1 = fabsf(v1) * 0.7071067811865475f;
    float t0 = __fdividef(1.0f, fmaf(0.3275911f, x0, 1.0f));
    float t1 = __fdividef(1.0f, fmaf(0.3275911f, x1, 1.0f));
    float e0 = -__expf(x0 * -x0);
    float e1 = -__expf(x1 * -x1);
    u64 t = pk(t0, t1);
    u64 p = fma2(t, pk(1.061405429f, 1.061405429f), pk(-1.453152027f, -1.453152027f));
    p = fma2(p, t, pk(1.421413741f, 1.421413741f));
    p = fma2(p, t, pk(-0.284496736f, -0.284496736f));
    p = fma2(p, t, pk(0.254829592f, 0.254829592f));
    p = mul2(p, t);
    u64 er = fma2(p, pk(e0, e1), pk(1.0f, 1.0f));
    er |= (v & 0x8000000080000000ULL);
    u64 u = fma2(er, pk(0.5f, 0.5f), pk(0.5f, 0.5f));
    return mul2(v, u);
}

__global__ void k_tables() {
    int k = blockIdx.x, y = threadIdx.x;
    int p = (k * y) & 255;
    float ang = (float)p * 0.024543692606170259f;
    float s, c; sincosf(ang, &s, &c);
    g_ctab[k*NPTS+y] = c;   g_stab[k*NPTS+y] = s;
    g_ctT[y*MODES+k] = c;   g_stT[y*MODES+k] = s;
}

__global__ void k_repack(const float* __restrict__ wr, const float* __restrict__ wi) {
    int blk = blockIdx.x;
    int l = blk >> 5, i = blk & 31;
    const float* wrb = wr + (size_t)blk * CH * MODES * MODES;
    const float* wib = wi + (size_t)blk * CH * MODES * MODES;
    for (int idx = threadIdx.x; idx < MODES*MODES*CH; idx += blockDim.x) {
        int o = idx & 31, kx = (idx >> 5) & 15, ky = idx >> 9;
        int s = o*(MODES*MODES) + kx*MODES + ky;
        g_Wp[(((size_t)(l*MODES+ky)*MODES+kx)*CH + i)*CH + o] = make_float2(wrb[s], wib[s]);
    }
}

__global__ void k_lift(const float* __restrict__ bc, const float* __restrict__ xin,
                       const float* __restrict__ yin, const float* __restrict__ mw,
                       const float* __restrict__ mb) {
    int blk = blockIdx.x;
    int b = blk >> 8, xi = blk & 255;
    int y = threadIdx.x;
    float b0 = bc[b*3+0], b1 = bc[b*3+1], b2 = bc[b*3+2];
    float xv = xin[(b*NPTS+xi)*NPTS + y];
    float yv = yin[(b*NPTS+xi)*NPTS + y];
    #pragma unroll
    for (int c = 0; c < CH; c++) {
        float h = mb[c] + b0*mw[c] + b1*mw[32+c] + b2*mw[64+c] + xv*mw[96+c] + yv*mw[128+c];
        g_h[((size_t)(b*CH+c)*NPTS + xi)*NPTS + y] = h;
    }
}

// fwd y-DFT: 2 modes (ks, ks+8) x 8 rows per thread; rotation recurrence, no smem.
// Rows share the trig states -> recurrence overhead ratio 16:64 (0.25 vs r9's 0.5).
__global__ __launch_bounds__(128) void k_fwd() {
    int tid = threadIdx.x;
    int blk = blockIdx.x;               // bcIdx*2 + xt
    int xt = blk & 1;
    int bcIdx = blk >> 1;
    int ks = tid & 7;                   // modes ks, ks+8
    int xg = tid >> 3;                  // 0..15
    int x0 = xt*128 + xg*8;
    const float4* h4 = (const float4*)(g_h + ((size_t)bcIdx*NPTS + x0)*NPTS);

    u64 cA[2], sA[2], cB[2], sB[2], C4[2], S4[2], nS4[2];
    #pragma unroll
    for (int m = 0; m < 2; m++) {
        float th = (float)(ks + 8*m) * 0.024543692606170259f;
        float c1,s1,c2,s2,c3,s3,c4,s4;
        sincosf(th,&s1,&c1);       sincosf(2.f*th,&s2,&c2);
        sincosf(3.f*th,&s3,&c3);   sincosf(4.f*th,&s4,&c4);
        cA[m]=pk(1.f,c1); sA[m]=pk(0.f,s1); cB[m]=pk(c2,c3); sB[m]=pk(s2,s3);
        C4[m]=pk(c4,c4);  S4[m]=pk(s4,s4);  nS4[m]=pk(-s4,-s4);
    }
    u64 ar[8][2], ai[8][2];
    #pragma unroll
    for (int r = 0; r < 8; r++) {
        ar[r][0]=0; ar[r][1]=0; ai[r][0]=0; ai[r][1]=0;
    }
    #pragma unroll 2
    for (int j = 0; j < 64; j++) {
        #pragma unroll
        for (int r = 0; r < 8; r++) {
            float4 v = h4[r*64 + j];
            u64 hlo = pk(v.x,v.y), hhi = pk(v.z,v.w);
            #pragma unroll
            for (int m = 0; m < 2; m++) {
                ar[r][m] = fma2(hlo, cA[m], ar[r][m]);
                ai[r][m] = fma2(hlo, sA[m], ai[r][m]);
                ar[r][m] = fma2(hhi, cB[m], ar[r][m]);
                ai[r][m] = fma2(hhi, sB[m], ai[r][m]);
            }
        }
        #pragma unroll
        for (int m = 0; m < 2; m++) {
            u64 cAn = mul2(cA[m], C4[m]); cAn = fma2(sA[m], nS4[m], cAn);
            u64 sAn = mul2(sA[m], C4[m]); sAn = fma2(cA[m], S4[m],  sAn);
            u64 cBn = mul2(cB[m], C4[m]); cBn = fma2(sB[m], nS4[m], cBn);
            u64 sBn = mul2(sB[m], C4[m]); sBn = fma2(cB[m], S4[m],  sBn);
            cA[m]=cAn; sA[m]=sAn; cB[m]=cBn; sB[m]=sBn;
        }
    }
    int b = bcIdx >> 5, c = bcIdx & 31;
    #pragma unroll
    for (int m = 0; m < 2; m++) {
        int ky = ks + 8*m;
        float2* outp = g_A + ((size_t)(b*MODES+ky)*CH + c)*NPTS + x0;
        #pragma unroll
        for (int r = 0; r < 8; r++) {
            float rl, rh, il, ih;
            upk(ar[r][m], rl, rh); upk(ai[r][m], il, ih);
            outp[r] = make_float2(rl + rh, -(il + ih));
        }
    }
}

__global__ __launch_bounds__(512) void k_spec(int layer) {
    __shared__ float2 Hft[CH*MODES];
    __shared__ float  Tmr[CH*17];
    __shared__ float  Tmi[CH*17];
    int tid = threadIdx.x;
    int b = blockIdx.x >> 4, ky = blockIdx.x & 15;
    {
        int c = tid >> 4, kx = tid & 15;
        const float2* Arow = g_A + ((size_t)(b*MODES+ky)*CH + c)*NPTS;
        float ar = 0.f, ai = 0.f;
        #pragma unroll 4
        for (int x = 0; x < 256; x++) {
            float2 a = Arow[x];
            float cc = g_ctT[x*16+kx], sv = g_stT[x*16+kx];
            ar += a.x*cc + a.y*sv;
            ai += a.y*cc - a.x*sv;
        }
        Hft[c*16+kx] = make_float2(ar*(1.0f/256.0f), ai*(1.0f/256.0f));
    }
    __syncthreads();
    {
        int kx = tid >> 5, o = tid & 31;
        const float2* W = g_Wp + ((size_t)((layer*MODES+ky)*MODES + kx)*CH)*CH;
        float tr = 0.f, ti = 0.f;
        #pragma unroll 8
        for (int i = 0; i < CH; i++) {
            float2 hh = Hft[i*16+kx];
            float2 w = W[i*32+o];
            tr += hh.x*w.x - hh.y*w.y;
            ti += hh.x*w.y + hh.y*w.x;
        }
        Tmr[o*17+kx] = tr;
        Tmi[o*17+kx] = ti;
    }
    __syncthreads();
    {
        int xg = tid >> 5, o = tid & 31;
        float Tr[16], Ti[16];
        #pragma unroll
        for (int k = 0; k < 16; k++) { Tr[k] = Tmr[o*17+k]; Ti[k] = Tmi[o*17+k]; }
        float scale = (ky == 0) ? (1.0f/256.0f) : (2.0f/256.0f);
        for (int j = 0; j < 16; j++) {
            int x = xg*16 + j;
            float br = 0.f, bi = 0.f;
            #pragma unroll
            for (int k = 0; k < 16; k++) {
                float cc = g_ctT[x*16+k], sv = g_stT[x*16+k];
                br += Tr[k]*cc - Ti[k]*sv;
                bi += Tr[k]*sv + Ti[k]*cc;
            }
            g_T2[((size_t)(b*NPTS+x)*MODES + ky)*CH + o] = make_float2(br*scale, bi*scale);
        }
    }
}

// combine: 128 threads, 2 y-points per thread (measured-good r9 version)
__global__ __launch_bounds__(128) void k_layer(const float* __restrict__ pww,
                                               const float* __restrict__ pwb, int layer) {
    __shared__ __align__(16) float T2r[MODES*CH];
    __shared__ __align__(16) float T2i[MODES*CH];
    __shared__ __align__(16) float wsP[CH*CH];
    __shared__ __align__(8)  float pbs[CH];
    int tid = threadIdx.x;
    int b = blockIdx.x >> 8, x = blockIdx.x & 255;

    {
        const float2* src = g_T2 + (size_t)(b*NPTS + x)*MODES*CH;
        #pragma unroll
        for (int t = 0; t < 4; t++) {
            float2 v = src[tid + 128*t];
            T2r[tid + 128*t] = v.x; T2i[tid + 128*t] = v.y;
        }
    }
    for (int idx = tid; idx < CH*CH; idx += 128) {
        int o = idx >> 5, i = idx & 31;
        wsP[i*32 + o] = pww[layer*CH*CH + idx];
    }
    if (tid < CH) pbs[tid] = pwb[layer*CH + tid];

    int y0 = 2*tid;
    u64 hd[CH];
    #pragma unroll
    for (int i = 0; i < CH; i++)
        hd[i] = *(const u64*)(g_h + ((size_t)(b*CH+i)*NPTS + x)*NPTS + y0);
    __syncthreads();

    u64 acc0[16], acc1[16];
    #pragma unroll
    for (int p = 0; p < 16; p++) {
        u64 bb = *(const u64*)&pbs[2*p];
        acc0[p] = bb; acc1[p] = bb;
    }
    #pragma unroll 2
    for (int i = 0; i < CH; i++) {
        float h0, h1; upk(hd[i], h0, h1);
        u64 d0 = pk(h0, h0), d1 = pk(h1, h1);
        #pragma unroll
        for (int q = 0; q < 8; q++) {
            u64x2 w = *(const u64x2*)&wsP[i*32 + 4*q];
            acc0[2*q]   = fma2(d0, w.x, acc0[2*q]);
            acc0[2*q+1] = fma2(d0, w.y, acc0[2*q+1]);
            acc1[2*q]   = fma2(d1, w.x, acc1[2*q]);
            acc1[2*q+1] = fma2(d1, w.y, acc1[2*q+1]);
        }
    }
    #pragma unroll 2
    for (int k = 0; k < 16; k++) {
        float c0, c1v, s0v, s1v;
        upk(*(const u64*)&g_ctab[k*NPTS + y0], c0, c1v);
        upk(*(const u64*)&g_stab[k*NPTS + y0], s0v, s1v);
        u64 cd0 = pk(c0, c0), cd1 = pk(c1v, c1v);
        u64 sd0 = pk(-s0v, -s0v), sd1 = pk(-s1v, -s1v);
        #pragma unroll
        for (int q = 0; q < 8; q++) {
            u64x2 tr = *(const u64x2*)&T2r[k*32 + 4*q];
            u64x2 ti = *(const u64x2*)&T2i[k*32 + 4*q];
            acc0[2*q]   = fma2(cd0, tr.x, acc0[2*q]);
            acc0[2*q+1] = fma2(cd0, tr.y, acc0[2*q+1]);
            acc0[2*q]   = fma2(sd0, ti.x, acc0[2*q]);
            acc0[2*q+1] = fma2(sd0, ti.y, acc0[2*q+1]);
            acc1[2*q]   = fma2(cd1, tr.x, acc1[2*q]);
            acc1[2*q+1] = fma2(cd1, tr.y, acc1[2*q+1]);
            acc1[2*q]   = fma2(sd1, ti.x, acc1[2*q]);
            acc1[2*q+1] = fma2(sd1, ti.y, acc1[2*q+1]);
        }
    }
    #pragma unroll
    for (int p = 0; p < 16; p++) {
        float ga0, gb0, ga1, gb1;
        upk(gelu2(acc0[p]), ga0, gb0);
        upk(gelu2(acc1[p]), ga1, gb1);
        int o = 2*p;
        float h0, h1;
        upk(hd[o], h0, h1);
        *(u64*)(g_h + ((size_t)(b*CH+o)*NPTS + x)*NPTS + y0) = pk(h0 + ga0, h1 + ga1);
        upk(hd[o+1], h0, h1);
        *(u64*)(g_h + ((size_t)(b*CH+o+1)*NPTS + x)*NPTS + y0) = pk(h0 + gb0, h1 + gb1);
    }
}

// decoders: one d per blockIdx.y; 64 threads, 4 points/thread (measured-good r9 version)
__global__ __launch_bounds__(64) void k_dec(
        const float* __restrict__ w1, const float* __restrict__ b1,
        const float* __restrict__ w2, const float* __restrict__ b2,
        const float* __restrict__ w3, const float* __restrict__ b3,
        float* __restrict__ out) {
    __shared__ __align__(16) u64 W1d[CH*CH];
    __shared__ __align__(16) u64 W2d[CH*HID];
    __shared__ __align__(16) u64 W3d[HID];
    __shared__ __align__(16) u64 B1d[CH];
    __shared__ __align__(16) u64 B2d[HID];
    int tid = threadIdx.x;
    int b = blockIdx.x >> 8, x = blockIdx.x & 255;
    int d = blockIdx.y;
    int y0 = 4*tid;

    for (int idx = tid; idx < CH*CH; idx += 64) {
        float w = w1[d*CH*CH + idx]; W1d[idx] = pk(w, w);
    }
    for (int idx = tid; idx < CH*HID; idx += 64) {
        float w = w2[d*CH*HID + idx]; W2d[idx] = pk(w, w);
    }
    for (int idx = tid; idx < HID; idx += 64) {
        float w = w3[d*HID + idx]; W3d[idx] = pk(w, w);
        float bb = b2[d*HID + idx]; B2d[idx] = pk(bb, bb);
    }
    if (tid < CH) { float bb = b1[d*CH + tid]; B1d[tid] = pk(bb, bb); }
    __syncthreads();

    u64 z0[CH], z1p[CH];
    #pragma unroll
    for (int pp = 0; pp < 2; pp++) {
        u64 hd[CH];
        #pragma unroll
        for (int i = 0; i < CH; i++)
            hd[i] = *(const u64*)(g_h + ((size_t)(b*CH+i)*NPTS + x)*NPTS + y0 + 2*pp);
        u64* z = pp ? z1p : z0;
        #pragma unroll 2
        for (int jp = 0; jp < CH/2; jp++) {
            u64 a0 = B1d[2*jp], a1 = B1d[2*jp+1];
            #pragma unroll
            for (int i = 0; i < CH; i++) {
                u64x2 w = *(const u64x2*)&W1d[i*CH + 2*jp];
                a0 = fma2(hd[i], w.x, a0);
                a1 = fma2(hd[i], w.y, a1);
            }
            z[2*jp]   = gelu2(a0);
            z[2*jp+1] = gelu2(a1);
        }
    }
    u64 o20 = 0, o21 = 0;
    #pragma unroll 2
    for (int jp = 0; jp < HID/2; jp++) {
        u64 a00 = B2d[2*jp], a01 = B2d[2*jp+1];
        u64 a10 = a00, a11 = a01;
        #pragma unroll
        for (int i = 0; i < CH; i++) {
            u64x2 w = *(const u64x2*)&W2d[i*HID + 2*jp];
            a00 = fma2(z0[i],  w.x, a00);
            a01 = fma2(z0[i],  w.y, a01);
            a10 = fma2(z1p[i], w.x, a10);
            a11 = fma2(z1p[i], w.y, a11);
        }
        o20 = fma2(gelu2(a00), W3d[2*jp],   o20);
        o20 = fma2(gelu2(a01), W3d[2*jp+1], o20);
        o21 = fma2(gelu2(a10), W3d[2*jp],   o21);
        o21 = fma2(gelu2(a11), W3d[2*jp+1], o21);
    }
    float r0, r1, r2, r3;
    upk(o20, r0, r1); upk(o21, r2, r3);
    float bias3 = b3[d];
    size_t p = ((size_t)(b*NPTS + x))*NPTS + y0;
    out[p*3 + d]       = r0 + bias3;
    out[(p+1)*3 + d]   = r1 + bias3;
    out[(p+2)*3 + d]   = r2 + bias3;
    out[(p+3)*3 + d]   = r3 + bias3;
}

extern "C" void kernel_launch(void* const* d_in, const int* in_sizes, int n_in,
                              void* d_out, int out_size) {
    const float* bc      = (const float*)d_in[0];
    const float* xin     = (const float*)d_in[1];
    const float* yin     = (const float*)d_in[2];
    const float* mlp1_w  = (const float*)d_in[3];
    const float* mlp1_b  = (const float*)d_in[4];
    const float* spec_wr = (const float*)d_in[5];
    const float* spec_wi = (const float*)d_in[6];
    const float* pw_w    = (const float*)d_in[7];
    const float* pw_b    = (const float*)d_in[8];
    const float* dec_w1  = (const float*)d_in[9];
    const float* dec_b1  = (const float*)d_in[10];
    const float* dec_w2  = (const float*)d_in[11];
    const float* dec_b2  = (const float*)d_in[12];
    const float* dec_w3  = (const float*)d_in[13];
    const float* dec_b3  = (const float*)d_in[14];
    float* out = (float*)d_out;

    k_tables<<<16, 256>>>();
    k_repack<<<NLAY*CH, 256>>>(spec_wr, spec_wi);
    k_lift<<<BATCH*NPTS, 256>>>(bc, xin, yin, mlp1_w, mlp1_b);
    for (int l = 0; l < NLAY; l++) {
        k_fwd<<<BATCH*CH*2, 128>>>();
        k_spec<<<BATCH*MODES, 512>>>(l);
        k_layer<<<BATCH*NPTS, 128>>>(pw_w, pw_b, l);
    }
    dim3 dgrid(BATCH*NPTS, 3);
    k_dec<<<dgrid, 64>>>(dec_w1, dec_b1, dec_w2, dec_b2, dec_w3, dec_b3, out);
}

// round 16
// speedup vs baseline: 1.2675x; 1.0035x over previous
#include <cuda_runtime.h>
#include <math.h>

#define BATCH 8
#define NPTS  256
#define CH    32
#define MODES 16
#define NLAY  4
#define HID   128

typedef unsigned long long u64;
typedef ulonglong2 u64x2;

__device__ __forceinline__ u64 pk(float lo, float hi) {
    u64 r; asm("mov.b64 %0, {%1, %2};" : "=l"(r) : "f"(lo), "f"(hi)); return r;
}
__device__ __forceinline__ void upk(u64 v, float& lo, float& hi) {
    asm("mov.b64 {%0, %1}, %2;" : "=f"(lo), "=f"(hi) : "l"(v));
}
__device__ __forceinline__ u64 fma2(u64 a, u64 b, u64 c) {
    u64 d; asm("fma.rn.f32x2 %0, %1, %2, %3;" : "=l"(d) : "l"(a), "l"(b), "l"(c)); return d;
}
__device__ __forceinline__ u64 mul2(u64 a, u64 b) { return fma2(a, b, 0ULL); }

__device__ float  g_h[BATCH*CH*NPTS*NPTS];
__device__ float2 g_A[BATCH*MODES*CH*NPTS];
__device__ float2 g_T2[BATCH*NPTS*MODES*CH];
__device__ float2 g_Wp[NLAY*MODES*MODES*CH*CH];
__device__ float  g_ctab[MODES*NPTS];
__device__ float  g_stab[MODES*NPTS];
__device__ float  g_ctT[NPTS*MODES];
__device__ float  g_stT[NPTS*MODES];

// gelu2: A&S 7.1.25 3-term erf (|err|<=2.5e-5), structure matching proven r9 form
__device__ __forceinline__ u64 gelu2(u64 v) {
    float v0, v1; upk(v, v0, v1);
    float x0 = fabsf(v0) * 0.7071067811865475f;
    float x1 = fabsf(v1) * 0.7071067811865475f;
    float t0 = __fdividef(1.0f, fmaf(0.47047f, x0, 1.0f));
    float t1 = __fdividef(1.0f, fmaf(0.47047f, x1, 1.0f));
    float e0 = -__expf(x0 * -x0);
    float e1 = -__expf(x1 * -x1);
    u64 t = pk(t0, t1);
    u64 p = fma2(t, pk(0.7478556f, 0.7478556f), pk(-0.0958798f, -0.0958798f));
    p = fma2(p, t, pk(0.3480242f, 0.3480242f));
    p = mul2(p, t);
    u64 er = fma2(p, pk(e0, e1), pk(1.0f, 1.0f));   // 1 - poly*exp(-x^2), in [0,1]
    er |= (v & 0x8000000080000000ULL);
    u64 u = fma2(er, pk(0.5f, 0.5f), pk(0.5f, 0.5f));
    return mul2(v, u);
}

__global__ void k_tables() {
    int k = blockIdx.x, y = threadIdx.x;
    int p = (k * y) & 255;
    float ang = (float)p * 0.024543692606170259f;
    float s, c; sincosf(ang, &s, &c);
    g_ctab[k*NPTS+y] = c;   g_stab[k*NPTS+y] = s;
    g_ctT[y*MODES+k] = c;   g_stT[y*MODES+k] = s;
}

__global__ void k_repack(const float* __restrict__ wr, const float* __restrict__ wi) {
    int blk = blockIdx.x;
    int l = blk >> 5, i = blk & 31;
    const float* wrb = wr + (size_t)blk * CH * MODES * MODES;
    const float* wib = wi + (size_t)blk * CH * MODES * MODES;
    for (int idx = threadIdx.x; idx < MODES*MODES*CH; idx += blockDim.x) {
        int o = idx & 31, kx = (idx >> 5) & 15, ky = idx >> 9;
        int s = o*(MODES*MODES) + kx*MODES + ky;
        g_Wp[(((size_t)(l*MODES+ky)*MODES+kx)*CH + i)*CH + o] = make_float2(wrb[s], wib[s]);
    }
}

__global__ void k_lift(const float* __restrict__ bc, const float* __restrict__ xin,
                       const float* __restrict__ yin, const float* __restrict__ mw,
                       const float* __restrict__ mb) {
    int blk = blockIdx.x;
    int b = blk >> 8, xi = blk & 255;
    int y = threadIdx.x;
    float b0 = bc[b*3+0], b1 = bc[b*3+1], b2 = bc[b*3+2];
    float xv = xin[(b*NPTS+xi)*NPTS + y];
    float yv = yin[(b*NPTS+xi)*NPTS + y];
    #pragma unroll
    for (int c = 0; c < CH; c++) {
        float h = mb[c] + b0*mw[c] + b1*mw[32+c] + b2*mw[64+c] + xv*mw[96+c] + yv*mw[128+c];
        g_h[((size_t)(b*CH+c)*NPTS + xi)*NPTS + y] = h;
    }
}

// fwd y-DFT: 2 modes (ks, ks+8) x 8 rows per thread; rotation recurrence, no smem.
// h loaded as u64x2 (no pk movs on the hot path).
__global__ __launch_bounds__(128) void k_fwd() {
    int tid = threadIdx.x;
    int blk = blockIdx.x;               // bcIdx*2 + xt
    int xt = blk & 1;
    int bcIdx = blk >> 1;
    int ks = tid & 7;                   // modes ks, ks+8
    int xg = tid >> 3;                  // 0..15
    int x0 = xt*128 + xg*8;
    const u64x2* h2 = (const u64x2*)(g_h + ((size_t)bcIdx*NPTS + x0)*NPTS);

    u64 cA[2], sA[2], cB[2], sB[2], C4[2], S4[2], nS4[2];
    #pragma unroll
    for (int m = 0; m < 2; m++) {
        float th = (float)(ks + 8*m) * 0.024543692606170259f;
        float c1,s1,c2,s2,c3,s3,c4,s4;
        sincosf(th,&s1,&c1);       sincosf(2.f*th,&s2,&c2);
        sincosf(3.f*th,&s3,&c3);   sincosf(4.f*th,&s4,&c4);
        cA[m]=pk(1.f,c1); sA[m]=pk(0.f,s1); cB[m]=pk(c2,c3); sB[m]=pk(s2,s3);
        C4[m]=pk(c4,c4);  S4[m]=pk(s4,s4);  nS4[m]=pk(-s4,-s4);
    }
    u64 ar[8][2], ai[8][2];
    #pragma unroll
    for (int r = 0; r < 8; r++) {
        ar[r][0]=0; ar[r][1]=0; ai[r][0]=0; ai[r][1]=0;
    }
    #pragma unroll 2
    for (int j = 0; j < 64; j++) {
        #pragma unroll
        for (int r = 0; r < 8; r++) {
            u64x2 hv = h2[r*64 + j];
            #pragma unroll
            for (int m = 0; m < 2; m++) {
                ar[r][m] = fma2(hv.x, cA[m], ar[r][m]);
                ai[r][m] = fma2(hv.x, sA[m], ai[r][m]);
                ar[r][m] = fma2(hv.y, cB[m], ar[r][m]);
                ai[r][m] = fma2(hv.y, sB[m], ai[r][m]);
            }
        }
        #pragma unroll
        for (int m = 0; m < 2; m++) {
            u64 cAn = mul2(cA[m], C4[m]); cAn = fma2(sA[m], nS4[m], cAn);
            u64 sAn = mul2(sA[m], C4[m]); sAn = fma2(cA[m], S4[m],  sAn);
            u64 cBn = mul2(cB[m], C4[m]); cBn = fma2(sB[m], nS4[m], cBn);
            u64 sBn = mul2(sB[m], C4[m]); sBn = fma2(cB[m], S4[m],  sBn);
            cA[m]=cAn; sA[m]=sAn; cB[m]=cBn; sB[m]=sBn;
        }
    }
    int b = bcIdx >> 5, c = bcIdx & 31;
    #pragma unroll
    for (int m = 0; m < 2; m++) {
        int ky = ks + 8*m;
        float2* outp = g_A + ((size_t)(b*MODES+ky)*CH + c)*NPTS + x0;
        #pragma unroll
        for (int r = 0; r < 8; r++) {
            float rl, rh, il, ih;
            upk(ar[r][m], rl, rh); upk(ai[r][m], il, ih);
            outp[r] = make_float2(rl + rh, -(il + ih));
        }
    }
}

__global__ __launch_bounds__(512) void k_spec(int layer) {
    __shared__ float2 Hft[CH*MODES];
    __shared__ float  Tmr[CH*17];
    __shared__ float  Tmi[CH*17];
    int tid = threadIdx.x;
    int b = blockIdx.x >> 4, ky = blockIdx.x & 15;
    {
        int c = tid >> 4, kx = tid & 15;
        const float2* Arow = g_A + ((size_t)(b*MODES+ky)*CH + c)*NPTS;
        float ar = 0.f, ai = 0.f;
        #pragma unroll 4
        for (int x = 0; x < 256; x++) {
            float2 a = Arow[x];
            float cc = g_ctT[x*16+kx], sv = g_stT[x*16+kx];
            ar += a.x*cc + a.y*sv;
            ai += a.y*cc - a.x*sv;
        }
        Hft[c*16+kx] = make_float2(ar*(1.0f/256.0f), ai*(1.0f/256.0f));
    }
    __syncthreads();
    {
        int kx = tid >> 5, o = tid & 31;
        const float2* W = g_Wp + ((size_t)((layer*MODES+ky)*MODES + kx)*CH)*CH;
        float tr = 0.f, ti = 0.f;
        #pragma unroll 8
        for (int i = 0; i < CH; i++) {
            float2 hh = Hft[i*16+kx];
            float2 w = W[i*32+o];
            tr += hh.x*w.x - hh.y*w.y;
            ti += hh.x*w.y + hh.y*w.x;
        }
        Tmr[o*17+kx] = tr;
        Tmi[o*17+kx] = ti;
    }
    __syncthreads();
    {
        int xg = tid >> 5, o = tid & 31;
        float Tr[16], Ti[16];
        #pragma unroll
        for (int k = 0; k < 16; k++) { Tr[k] = Tmr[o*17+k]; Ti[k] = Tmi[o*17+k]; }
        float scale = (ky == 0) ? (1.0f/256.0f) : (2.0f/256.0f);
        for (int j = 0; j < 16; j++) {
            int x = xg*16 + j;
            float br = 0.f, bi = 0.f;
            #pragma unroll
            for (int k = 0; k < 16; k++) {
                float cc = g_ctT[x*16+k], sv = g_stT[x*16+k];
                br += Tr[k]*cc - Ti[k]*sv;
                bi += Tr[k]*sv + Ti[k]*cc;
            }
            g_T2[((size_t)(b*NPTS+x)*MODES + ky)*CH + o] = make_float2(br*scale, bi*scale);
        }
    }
}

// combine: 128 threads, 2 y-points per thread (measured-good r9 version)
__global__ __launch_bounds__(128) void k_layer(const float* __restrict__ pww,
                                               const float* __restrict__ pwb, int layer) {
    __shared__ __align__(16) float T2r[MODES*CH];
    __shared__ __align__(16) float T2i[MODES*CH];
    __shared__ __align__(16) float wsP[CH*CH];
    __shared__ __align__(8)  float pbs[CH];
    int tid = threadIdx.x;
    int b = blockIdx.x >> 8, x = blockIdx.x & 255;

    {
        const float2* src = g_T2 + (size_t)(b*NPTS + x)*MODES*CH;
        #pragma unroll
        for (int t = 0; t < 4; t++) {
            float2 v = src[tid + 128*t];
            T2r[tid + 128*t] = v.x; T2i[tid + 128*t] = v.y;
        }
    }
    for (int idx = tid; idx < CH*CH; idx += 128) {
        int o = idx >> 5, i = idx & 31;
        wsP[i*32 + o] = pww[layer*CH*CH + idx];
    }
    if (tid < CH) pbs[tid] = pwb[layer*CH + tid];

    int y0 = 2*tid;
    u64 hd[CH];
    #pragma unroll
    for (int i = 0; i < CH; i++)
        hd[i] = *(const u64*)(g_h + ((size_t)(b*CH+i)*NPTS + x)*NPTS + y0);
    __syncthreads();

    u64 acc0[16], acc1[16];
    #pragma unroll
    for (int p = 0; p < 16; p++) {
        u64 bb = *(const u64*)&pbs[2*p];
        acc0[p] = bb; acc1[p] = bb;
    }
    #pragma unroll 2
    for (int i = 0; i < CH; i++) {
        float h0, h1; upk(hd[i], h0, h1);
        u64 d0 = pk(h0, h0), d1 = pk(h1, h1);
        #pragma unroll
        for (int q = 0; q < 8; q++) {
            u64x2 w = *(const u64x2*)&wsP[i*32 + 4*q];
            acc0[2*q]   = fma2(d0, w.x, acc0[2*q]);
            acc0[2*q+1] = fma2(d0, w.y, acc0[2*q+1]);
            acc1[2*q]   = fma2(d1, w.x, acc1[2*q]);
            acc1[2*q+1] = fma2(d1, w.y, acc1[2*q+1]);
        }
    }
    #pragma unroll 2
    for (int k = 0; k < 16; k++) {
        float c0, c1v, s0v, s1v;
        upk(*(const u64*)&g_ctab[k*NPTS + y0], c0, c1v);
        upk(*(const u64*)&g_stab[k*NPTS + y0], s0v, s1v);
        u64 cd0 = pk(c0, c0), cd1 = pk(c1v, c1v);
        u64 sd0 = pk(-s0v, -s0v), sd1 = pk(-s1v, -s1v);
        #pragma unroll
        for (int q = 0; q < 8; q++) {
            u64x2 tr = *(const u64x2*)&T2r[k*32 + 4*q];
            u64x2 ti = *(const u64x2*)&T2i[k*32 + 4*q];
            acc0[2*q]   = fma2(cd0, tr.x, acc0[2*q]);
            acc0[2*q+1] = fma2(cd0, tr.y, acc0[2*q+1]);
            acc0[2*q]   = fma2(sd0, ti.x, acc0[2*q]);
            acc0[2*q+1] = fma2(sd0, ti.y, acc0[2*q+1]);
            acc1[2*q]   = fma2(cd1, tr.x, acc1[2*q]);
            acc1[2*q+1] = fma2(cd1, tr.y, acc1[2*q+1]);
            acc1[2*q]   = fma2(sd1, ti.x, acc1[2*q]);
            acc1[2*q+1] = fma2(sd1, ti.y, acc1[2*q+1]);
        }
    }
    #pragma unroll
    for (int p = 0; p < 16; p++) {
        float ga0, gb0, ga1, gb1;
        upk(gelu2(acc0[p]), ga0, gb0);
        upk(gelu2(acc1[p]), ga1, gb1);
        int o = 2*p;
        float h0, h1;
        upk(hd[o], h0, h1);
        *(u64*)(g_h + ((size_t)(b*CH+o)*NPTS + x)*NPTS + y0) = pk(h0 + ga0, h1 + ga1);
        upk(hd[o+1], h0, h1);
        *(u64*)(g_h + ((size_t)(b*CH+o+1)*NPTS + x)*NPTS + y0) = pk(h0 + gb0, h1 + gb1);
    }
}

// decoders: one d per blockIdx.y; 64 threads, 4 points/thread (measured-good r9 version)
__global__ __launch_bounds__(64) void k_dec(
        const float* __restrict__ w1, const float* __restrict__ b1,
        const float* __restrict__ w2, const float* __restrict__ b2,
        const float* __restrict__ w3, const float* __restrict__ b3,
        float* __restrict__ out) {
    __shared__ __align__(16) u64 W1d[CH*CH];
    __shared__ __align__(16) u64 W2d[CH*HID];
    __shared__ __align__(16) u64 W3d[HID];
    __shared__ __align__(16) u64 B1d[CH];
    __shared__ __align__(16) u64 B2d[HID];
    int tid = threadIdx.x;
    int b = blockIdx.x >> 8, x = blockIdx.x & 255;
    int d = blockIdx.y;
    int y0 = 4*tid;

    for (int idx = tid; idx < CH*CH; idx += 64) {
        float w = w1[d*CH*CH + idx]; W1d[idx] = pk(w, w);
    }
    for (int idx = tid; idx < CH*HID; idx += 64) {
        float w = w2[d*CH*HID + idx]; W2d[idx] = pk(w, w);
    }
    for (int idx = tid; idx < HID; idx += 64) {
        float w = w3[d*HID + idx]; W3d[idx] = pk(w, w);
        float bb = b2[d*HID + idx]; B2d[idx] = pk(bb, bb);
    }
    if (tid < CH) { float bb = b1[d*CH + tid]; B1d[tid] = pk(bb, bb); }
    __syncthreads();

    u64 z0[CH], z1p[CH];
    #pragma unroll
    for (int pp = 0; pp < 2; pp++) {
        u64 hd[CH];
        #pragma unroll
        for (int i = 0; i < CH; i++)
            hd[i] = *(const u64*)(g_h + ((size_t)(b*CH+i)*NPTS + x)*NPTS + y0 + 2*pp);
        u64* z = pp ? z1p : z0;
        #pragma unroll 2
        for (int jp = 0; jp < CH/2; jp++) {
            u64 a0 = B1d[2*jp], a1 = B1d[2*jp+1];
            #pragma unroll
            for (int i = 0; i < CH; i++) {
                u64x2 w = *(const u64x2*)&W1d[i*CH + 2*jp];
                a0 = fma2(hd[i], w.x, a0);
                a1 = fma2(hd[i], w.y, a1);
            }
            z[2*jp]   = gelu2(a0);
            z[2*jp+1] = gelu2(a1);
        }
    }
    u64 o20 = 0, o21 = 0;
    #pragma unroll 2
    for (int jp = 0; jp < HID/2; jp++) {
        u64 a00 = B2d[2*jp], a01 = B2d[2*jp+1];
        u64 a10 = a00, a11 = a01;
        #pragma unroll
        for (int i = 0; i < CH; i++) {
            u64x2 w = *(const u64x2*)&W2d[i*HID + 2*jp];
            a00 = fma2(z0[i],  w.x, a00);
            a01 = fma2(z0[i],  w.y, a01);
            a10 = fma2(z1p[i], w.x, a10);
            a11 = fma2(z1p[i], w.y, a11);
        }
        o20 = fma2(gelu2(a00), W3d[2*jp],   o20);
        o20 = fma2(gelu2(a01), W3d[2*jp+1], o20);
        o21 = fma2(gelu2(a10), W3d[2*jp],   o21);
        o21 = fma2(gelu2(a11), W3d[2*jp+1], o21);
    }
    float r0, r1, r2, r3;
    upk(o20, r0, r1); upk(o21, r2, r3);
    float bias3 = b3[d];
    size_t p = ((size_t)(b*NPTS + x))*NPTS + y0;
    out[p*3 + d]       = r0 + bias3;
    out[(p+1)*3 + d]   = r1 + bias3;
    out[(p+2)*3 + d]   = r2 + bias3;
    out[(p+3)*3 + d]   = r3 + bias3;
}

extern "C" void kernel_launch(void* const* d_in, const int* in_sizes, int n_in,
                              void* d_out, int out_size) {
    const float* bc      = (const float*)d_in[0];
    const float* xin     = (const float*)d_in[1];
    const float* yin     = (const float*)d_in[2];
    const float* mlp1_w  = (const float*)d_in[3];
    const float* mlp1_b  = (const float*)d_in[4];
    const float* spec_wr = (const float*)d_in[5];
    const float* spec_wi = (const float*)d_in[6];
    const float* pw_w    = (const float*)d_in[7];
    const float* pw_b    = (const float*)d_in[8];
    const float* dec_w1  = (const float*)d_in[9];
    const float* dec_b1  = (const float*)d_in[10];
    const float* dec_w2  = (const float*)d_in[11];
    const float* dec_b2  = (const float*)d_in[12];
    const float* dec_w3  = (const float*)d_in[13];
    const float* dec_b3  = (const float*)d_in[14];
    float* out = (float*)d_out;

    k_tables<<<16, 256>>>();
    k_repack<<<NLAY*CH, 256>>>(spec_wr, spec_wi);
    k_lift<<<BATCH*NPTS, 256>>>(bc, xin, yin, mlp1_w, mlp1_b);
    for (int l = 0; l < NLAY; l++) {
        k_fwd<<<BATCH*CH*2, 128>>>();
        k_spec<<<BATCH*MODES, 512>>>(l);
        k_layer<<<BATCH*NPTS, 128>>>(pw_w, pw_b, l);
    }
    dim3 dgrid(BATCH*NPTS, 3);
    k_dec<<<dgrid, 64>>>(dec_w1, dec_b1, dec_w2, dec_b2, dec_w3, dec_b3, out);
}